// round 14
// baseline (speedup 1.0000x reference)
#include <cuda_runtime.h>
#include <cuda_bf16.h>
#include <math.h>

// Problem constants
#define NXX   729
#define NEQX  300
#define BAT   16
#define LDSM  320                 // rows line-aligned: 320*4B = 10 x 128B lines
#define SSTR  (NEQX*LDSM)
#define NPAN  10
#define NB    10
#define CLW   5                   // 10 blocks / 5 CTAs = exactly 2 each
#define SIGC  0.1f
#define BIGV  1e9f

// ---------------- device scratch ----------------
__device__ float g_P   [BAT*NXX];
__device__ float g_Z   [BAT*NXX];
__device__ float g_Sl  [BAT*NXX];
__device__ float g_Lm  [BAT*NXX];
__device__ float g_Qt  [BAT*NXX];
__device__ float g_NU  [BAT*NEQX];
__device__ float g_RHS [BAT*NEQX];
__device__ float g_Smat[BAT*SSTR];
__device__ float g_S0  [SSTR];
__device__ float g_Minv[BAT*NPAN*1024];
__device__ float g_Minv0[NPAN*1024];
__device__ float g_Qd  [NXX];
__device__ float g_Hinv0[NXX];
__device__ float g_MU  [BAT];      // mu of CURRENT state (used by syrk-RHS + stepsolve)

__device__ __forceinline__ void cluster_sync_() {
    asm volatile("barrier.cluster.arrive.aligned;" ::: "memory");
    asm volatile("barrier.cluster.wait.aligned;" ::: "memory");
}

// ---------------- reductions ----------------
__device__ __forceinline__ float blkSum(float v, float* red) {
    #pragma unroll
    for (int o = 16; o; o >>= 1) v += __shfl_xor_sync(0xffffffffu, v, o);
    int w = threadIdx.x >> 5;
    if ((threadIdx.x & 31) == 0) red[w] = v;
    __syncthreads();
    if (threadIdx.x < 32) {
        int nw = blockDim.x >> 5;
        v = (threadIdx.x < nw) ? red[threadIdx.x] : 0.f;
        #pragma unroll
        for (int o = 16; o; o >>= 1) v += __shfl_xor_sync(0xffffffffu, v, o);
        if (threadIdx.x == 0) red[0] = v;
    }
    __syncthreads();
    return red[0];
}

__device__ __forceinline__ float blkMin(float v, float* red) {
    #pragma unroll
    for (int o = 16; o; o >>= 1) v = fminf(v, __shfl_xor_sync(0xffffffffu, v, o));
    int w = threadIdx.x >> 5;
    if ((threadIdx.x & 31) == 0) red[w] = v;
    __syncthreads();
    if (threadIdx.x < 32) {
        int nw = blockDim.x >> 5;
        v = (threadIdx.x < nw) ? red[threadIdx.x] : BIGV;
        #pragma unroll
        for (int o = 16; o; o >>= 1) v = fminf(v, __shfl_xor_sync(0xffffffffu, v, o));
        if (threadIdx.x == 0) red[0] = v;
    }
    __syncthreads();
    return red[0];
}

// ---------------- setup ----------------
__global__ void k_setup(const float* __restrict__ puz, const float* __restrict__ Q) {
    int b = blockIdx.x, i = threadIdx.x;
    if (i < NXX) {
        g_P[b*NXX + i] = -puz[b*NXX + i];
        if (b == 0) {
            float qd = Q[i*NXX + i];
            g_Qd[i] = qd;
            g_Hinv0[i] = 1.0f / qd;
        }
    }
}

// ---------------- batched SYRK + fused residual RHS ------------------------
// S = A diag(hinv) A^T with hinv computed INLINE from state (no k_res).
// Diagonal tiles (ti==tj) additionally compute su[k] = r1*hinv + z on the fly
// and accumulate the next-iteration RHS = A su - b for their 64 rows, riding
// on the A loads the SYRK already performs (full width, zero extra traffic).
__global__ void __launch_bounds__(256) k_syrk(const float* __restrict__ A,
                                              const float* __restrict__ bvec,
                                              const float* __restrict__ h,
                                              int init) {
    int t = blockIdx.x, b = blockIdx.y;
    int ti = 0;
    while ((ti + 1) * (ti + 2) / 2 <= t) ti++;
    int tj = t - ti * (ti + 1) / 2;
    float* Sout = init ? g_S0 : (g_Smat + b*SSTR);
    bool diag = (!init) && (ti == tj);
    float muv = diag ? g_MU[b] : 0.f;

    __shared__ __align__(16) float As[32*68];
    __shared__ __align__(16) float Bs[32*68];

    int tid = threadIdx.x;
    int tx = tid & 15, ty = tid >> 4;
    float acc[4][4];
    #pragma unroll
    for (int u = 0; u < 4; u++)
        #pragma unroll
        for (int v = 0; v < 4; v++) acc[u][v] = 0.f;
    float rhsacc[8];
    #pragma unroll
    for (int l = 0; l < 8; l++) rhsacc[l] = 0.f;

    int row0 = ti * 64, col0 = tj * 64;
    int cld = tid & 31, rbase = tid >> 5;

    for (int k0 = 0; k0 < NXX; k0 += 32) {
        int k = k0 + cld;
        bool kok = (k < NXX);
        float hval = 0.f, suv = 0.f;
        if (kok) {
            if (init) {
                hval = g_Hinv0[k];
            } else {
                float sl = g_Sl[b*NXX + k];
                float lm = g_Lm[b*NXX + k];
                float qd = g_Qd[k];
                hval = 1.0f / (qd + lm/sl);
                if (diag) {
                    float z  = g_Z [b*NXX + k];
                    float pi = g_P [b*NXX + k];
                    float q  = g_Qt[b*NXX + k];
                    float hi = h[k];
                    float rz = qd*z + pi - lm + q;      // G^T lam = -lam
                    float rp = sl - z - hi;             // G z + s - h
                    float rs = sl*lm - SIGC*muv;
                    float r1 = -rz + (lm*rp - rs)/sl;
                    suv = r1*hval + z;
                }
            }
        }
        #pragma unroll
        for (int l = 0; l < 8; l++) {
            int r = rbase + l * 8;
            int gi = row0 + r;
            int gj = col0 + r;
            float av  = (kok && gi < NEQX) ? A[gi*NXX + k] : 0.f;
            float bvv = (kok && gj < NEQX) ? A[gj*NXX + k] : 0.f;
            As[cld*68 + r] = av * hval;
            Bs[cld*68 + r] = bvv;
            if (diag) rhsacc[l] += av * suv;
        }
        __syncthreads();
        #pragma unroll
        for (int kk = 0; kk < 32; kk++) {
            float4 a4 = *reinterpret_cast<const float4*>(&As[kk*68 + (ty << 2)]);
            float4 b4 = *reinterpret_cast<const float4*>(&Bs[kk*68 + (tx << 2)]);
            float av[4] = {a4.x, a4.y, a4.z, a4.w};
            float bv4[4] = {b4.x, b4.y, b4.z, b4.w};
            #pragma unroll
            for (int u = 0; u < 4; u++)
                #pragma unroll
                for (int v = 0; v < 4; v++) acc[u][v] += av[u] * bv4[v];
        }
        __syncthreads();
    }
    #pragma unroll
    for (int u = 0; u < 4; u++) {
        int gi = row0 + (ty << 2) + u;
        #pragma unroll
        for (int v = 0; v < 4; v++) {
            int gj = col0 + (tx << 2) + v;
            if (gi < NEQX && gj < NEQX && gj <= gi)
                Sout[gi*LDSM + gj] = acc[u][v];
        }
    }
    // RHS write: warp-reduce each of the 8 row partials over lanes (k)
    if (diag) {
        #pragma unroll
        for (int l = 0; l < 8; l++) {
            float v = rhsacc[l];
            #pragma unroll
            for (int o = 16; o; o >>= 1) v += __shfl_xor_sync(0xffffffffu, v, o);
            int row = row0 + rbase + l * 8;
            if (cld == 0 && row < NEQX)
                g_RHS[b*NEQX + row] = v - bvec[row];
        }
    }
}

// ---------------- cluster-parallel right-looking Cholesky (R8/R12) --------
__global__ void __launch_bounds__(256) __cluster_dims__(CLW, 1, 1)
k_chol(int init) {
    int batch = blockIdx.x / CLW;
    unsigned crank;
    asm("mov.u32 %0, %%cluster_ctarank;" : "=r"(crank));
    float* S    = init ? g_S0    : (g_Smat + batch*SSTR);
    float* Minv = init ? g_Minv0 : (g_Minv + batch*(NPAN*1024));
    int tid = threadIdx.x;
    int lane = tid & 31;
    int wid = tid >> 5;

    __shared__ float ld[32*33];
    __shared__ float mi[32*33];
    __shared__ float tT[16*17];
    __shared__ float sinvd[32];
    __shared__ float pan[64*33];

    for (int p = 0; p < NPAN; p++) {
        int col0 = p * 32;
        int pw = NEQX - col0; if (pw > 32) pw = 32;
        int owner = p % CLW;

        cluster_sync_();

        if (wid == 0) {
            float row[32];
            #pragma unroll
            for (int j = 0; j < 32; j++)
                row[j] = (lane < pw && j < pw) ? S[(col0+lane)*LDSM + col0 + j] : 0.f;
            float sinv = 0.f;
            #pragma unroll
            for (int c = 0; c < 32; c++) {
                if (c < pw) {
                    float piv = __shfl_sync(0xffffffffu, row[c], c);
                    float inv = rsqrtf(piv);
                    float d   = piv * inv;
                    float lrc;
                    if (lane == c)      lrc = d;
                    else if (lane > c)  lrc = row[c] * inv;
                    else                lrc = 0.f;
                    row[c] = lrc;
                    if (lane == c) sinv = 1.0f / d;
                    #pragma unroll
                    for (int j = 0; j < 32; j++) {
                        if (j > c) {
                            float ljc = __shfl_sync(0xffffffffu, lrc, j);
                            row[j] -= lrc * ljc;
                        }
                    }
                }
            }
            sinvd[lane] = sinv;
            #pragma unroll
            for (int j = 0; j < 32; j++) ld[lane*33 + j] = row[j];
            if ((int)crank == owner && lane < pw) {
                #pragma unroll
                for (int j = 0; j < 32; j++)
                    S[(col0+lane)*LDSM + col0 + j] = row[j];
            }
        } else {
            #pragma unroll
            for (int s = 0; s < 2; s++) {
                int bi = (int)crank + s*CLW;
                if (bi <= p) continue;
                int nr = NEQX - bi*32; if (nr > 32) nr = 32;
                for (int idx = tid - 32; idx < 1024; idx += 224) {
                    int r = idx >> 5, c = idx & 31;
                    pan[(s*32+r)*33 + c] = (r < nr && c < pw)
                        ? S[(bi*32+r)*LDSM + col0 + c] : 0.f;
                }
            }
        }
        __syncthreads();

        if (wid == 0) {
            int c = lane & 15;
            int half = lane >> 4;
            int base = half << 4;
            float xc[16];
            #pragma unroll
            for (int j = 0; j < 16; j++) xc[j] = 0.f;
            xc[c] = sinvd[base + c];
            #pragma unroll
            for (int rr = 1; rr < 16; rr++) {
                float s = 0.f;
                #pragma unroll
                for (int j = 0; j < 16; j++)
                    if (j < rr) s += ld[(base+rr)*33 + base + j] * xc[j];
                if (rr > c) xc[rr] = -s * sinvd[base + rr];
            }
            #pragma unroll
            for (int rr = 0; rr < 16; rr++) {
                mi[(base+rr)*33 + base + c] = xc[rr];
                if (half == 0) mi[rr*33 + 16 + c] = 0.f;
            }
            __syncwarp();
            {
                int cc = lane & 15;
                int r0 = (lane >> 4) * 8;
                #pragma unroll
                for (int r = 0; r < 8; r++) {
                    float s = 0.f;
                    #pragma unroll
                    for (int j = 0; j < 16; j++)
                        s += ld[(16 + r0 + r)*33 + j] * mi[j*33 + cc];
                    tT[(r0 + r)*17 + cc] = s;
                }
            }
            __syncwarp();
            {
                int cc = lane & 15;
                int r0 = (lane >> 4) * 8;
                #pragma unroll
                for (int r = 0; r < 8; r++) {
                    float s = 0.f;
                    #pragma unroll
                    for (int j = 0; j < 16; j++)
                        s += mi[(16 + r0 + r)*33 + 16 + j] * tT[j*17 + cc];
                    mi[(16 + r0 + r)*33 + cc] = -s;
                }
            }
            __syncwarp();
            if ((int)crank == owner) {
                float* Mp = Minv + p * 1024;
                #pragma unroll
                for (int rr = 0; rr < 32; rr++)
                    Mp[rr*32 + lane] = mi[rr*33 + lane];
            }
        }
        __syncthreads();

        #pragma unroll
        for (int s = 0; s < 2; s++) {
            int bi = (int)crank + s*CLW;
            if (bi <= p) continue;
            int r  = tid >> 3;
            int c0 = (tid & 7) << 2;
            float breg[32];
            #pragma unroll
            for (int j = 0; j < 32; j++) breg[j] = pan[(s*32+r)*33 + j];
            float a0=0.f, a1=0.f, a2=0.f, a3=0.f;
            #pragma unroll
            for (int j = 0; j < 32; j++) {
                float bj = breg[j];
                a0 += bj * mi[(c0+0)*33 + j];
                a1 += bj * mi[(c0+1)*33 + j];
                a2 += bj * mi[(c0+2)*33 + j];
                a3 += bj * mi[(c0+3)*33 + j];
            }
            __syncwarp();
            pan[(s*32+r)*33 + c0 + 0] = a0;
            pan[(s*32+r)*33 + c0 + 1] = a1;
            pan[(s*32+r)*33 + c0 + 2] = a2;
            pan[(s*32+r)*33 + c0 + 3] = a3;
        }
        __syncthreads();

        #pragma unroll
        for (int s = 0; s < 2; s++) {
            int bi = (int)crank + s*CLW;
            if (bi <= p) continue;
            int nr = NEQX - bi*32; if (nr > 32) nr = 32;
            for (int idx = tid; idx < 1024; idx += 256) {
                int r = idx >> 5, c = idx & 31;
                if (r < nr && c < pw)
                    S[(bi*32+r)*LDSM + col0 + c] = pan[(s*32+r)*33 + c];
            }
            for (int idx = tid; idx < 1024; idx += 256) {
                int c = idx >> 5, r = idx & 31;
                if (r < nr && c < pw)
                    S[(col0+c)*LDSM + bi*32 + r] = pan[(s*32+r)*33 + c];
            }
        }
        cluster_sync_();

        {
            int tcount = 0;
            #pragma unroll
            for (int s = 0; s < 2; s++) {
                int bi = (int)crank + s*CLW;
                if (bi <= p) continue;
                int nri = NEQX - bi*32; if (nri > 32) nri = 32;
                for (int jb = p + 1; jb <= bi; jb++) {
                    if ((tcount++ & 7) != wid) continue;
                    int nrj = NEQX - jb*32; if (nrj > 32) nrj = 32;
                    bool cok = (lane < nrj);
                    float xjr[32];
                    #pragma unroll
                    for (int k = 0; k < 32; k++)
                        xjr[k] = cok ? S[(col0+k)*LDSM + jb*32 + lane] : 0.f;
                    for (int r = 0; r < nri; r++) {
                        float acc = 0.f;
                        #pragma unroll
                        for (int k = 0; k < 32; k++)
                            acc += pan[(s*32+r)*33 + k] * xjr[k];
                        if (cok)
                            S[(size_t)(bi*32+r)*LDSM + jb*32 + lane] -= acc;
                    }
                }
            }
        }
    }
}

// ---------------- standalone triangular solve (init only) -----------------
__global__ void __launch_bounds__(320) k_trsolve(int init) {
    int b = blockIdx.x;
    const float* S    = init ? g_S0    : (g_Smat + b*SSTR);
    const float* Minv = init ? g_Minv0 : (g_Minv + b*(NPAN*1024));
    const float* rhs  = g_RHS + b*NEQX;
    float* out        = g_NU + b*NEQX;
    __shared__ float sy[320];
    __shared__ float mv[32*33];
    int tid = threadIdx.x;
    int lane = tid & 31;
    sy[tid] = (tid < NEQX) ? rhs[tid] : 0.f;
    __syncthreads();
    for (int p = 0; p < NPAN; p++) {
        int col0 = p * 32;
        int pw = NEQX - col0; if (pw > 32) pw = 32;
        const float* Mp = Minv + p * 1024;
        for (int idx = tid; idx < 1024; idx += 320) {
            int i = idx >> 5, j = idx & 31;
            mv[i*33 + j] = Mp[i*32 + j];
        }
        __syncthreads();
        if (tid < 32) {
            float y = 0.f;
            #pragma unroll 8
            for (int j = 0; j < 32; j++) y += mv[lane*33 + j] * sy[col0 + j];
            __syncwarp();
            if (lane < pw) sy[col0 + lane] = y;
        }
        __syncthreads();
        int rem = NEQX - col0 - pw;
        if (tid < rem) {
            int i = col0 + pw + tid;
            float s = 0.f;
            #pragma unroll 8
            for (int c = 0; c < 32; c++)
                if (c < pw) s += S[(col0 + c)*LDSM + i] * sy[col0 + c];
            sy[i] -= s;
        }
        __syncthreads();
    }
    for (int p = NPAN - 1; p >= 0; p--) {
        int col0 = p * 32;
        int pw = NEQX - col0; if (pw > 32) pw = 32;
        const float* Mp = Minv + p * 1024;
        for (int idx = tid; idx < 1024; idx += 320) {
            int i = idx >> 5, j = idx & 31;
            mv[i*33 + j] = Mp[i*32 + j];
        }
        __syncthreads();
        if (tid < 32) {
            float x = 0.f;
            #pragma unroll 8
            for (int j = 0; j < 32; j++) x += mv[j*33 + lane] * sy[col0 + j];
            __syncwarp();
            if (lane < pw) sy[col0 + lane] = x;
        }
        __syncthreads();
        if (tid < col0) {
            float s = 0.f;
            #pragma unroll 8
            for (int c = 0; c < 32; c++)
                if (c < pw) s += S[(col0 + c)*LDSM + tid] * sy[col0 + c];
            sy[tid] -= s;
        }
        __syncthreads();
    }
    if (tid < NEQX) out[tid] = sy[tid];
}

// ---------------- fused trsolve + step (+ mu); residuals recomputed inline -
__global__ void __launch_bounds__(768) k_stepsolve(const float* __restrict__ A,
                                                   const float* __restrict__ h) {
    int b = blockIdx.x, tid = threadIdx.x, lane = tid & 31;
    const float* S    = g_Smat + b*SSTR;
    const float* Minv = g_Minv + b*(NPAN*1024);
    __shared__ float sy[320];
    __shared__ float miAll[NPAN*32*33];   // 42.2 KB: all 10 panel inverses
    __shared__ float red[32];
    if (tid < 320) sy[tid] = (tid < NEQX) ? g_RHS[b*NEQX + tid] : 0.f;
    for (int idx = tid; idx < NPAN*1024; idx += 768) {
        int p = idx >> 10;
        int e = idx & 1023;
        miAll[p*(32*33) + (e >> 5)*33 + (e & 31)] = Minv[idx];
    }
    __syncthreads();

    // forward: L y = rhs
    for (int p = 0; p < NPAN; p++) {
        int col0 = p * 32;
        int pw = NEQX - col0; if (pw > 32) pw = 32;
        const float* mv = miAll + p*(32*33);
        if (tid < 32) {
            float y = 0.f;
            #pragma unroll 8
            for (int j = 0; j < 32; j++) y += mv[lane*33 + j] * sy[col0 + j];
            __syncwarp();
            if (lane < pw) sy[col0 + lane] = y;
        }
        __syncthreads();
        int rem = NEQX - col0 - pw;
        if (tid < rem) {
            int i = col0 + pw + tid;
            float s = 0.f;
            #pragma unroll 8
            for (int c = 0; c < 32; c++)
                if (c < pw) s += S[(col0 + c)*LDSM + i] * sy[col0 + c];
            sy[i] -= s;
        }
        __syncthreads();
    }
    // backward: L^T x = y
    for (int p = NPAN - 1; p >= 0; p--) {
        int col0 = p * 32;
        int pw = NEQX - col0; if (pw > 32) pw = 32;
        const float* mv = miAll + p*(32*33);
        if (tid < 32) {
            float x = 0.f;
            #pragma unroll 8
            for (int j = 0; j < 32; j++) x += mv[j*33 + lane] * sy[col0 + j];
            __syncwarp();
            if (lane < pw) sy[col0 + lane] = x;
        }
        __syncthreads();
        if (tid < col0) {
            float s = 0.f;
            #pragma unroll 8
            for (int c = 0; c < 32; c++)
                if (c < pw) s += S[(col0 + c)*LDSM + tid] * sy[col0 + c];
            sy[tid] -= s;
        }
        __syncthreads();
    }
    // sy now holds dnu

    // step phase: residuals recomputed inline (mu of current state in g_MU)
    float muv = g_MU[b];
    float cand = BIGV;
    float t = 0.f, dz = 0.f, ds = 0.f, dlam = 0.f, si = 0.f, li = 0.f;
    if (tid < NXX) {
        #pragma unroll 8
        for (int j = 0; j < NEQX; j++) t += A[j*NXX + tid] * sy[j];
        si = g_Sl[b*NXX + tid];
        li = g_Lm[b*NXX + tid];
        float zi  = g_Z [b*NXX + tid];
        float qtv = g_Qt[b*NXX + tid];
        float qd  = g_Qd[tid];
        float pi  = g_P [b*NXX + tid];
        float hi  = h[tid];
        float rz = qd*zi + pi - li + qtv;
        float rp = si - zi - hi;
        float rs = si*li - SIGC*muv;
        float hinv = 1.0f/(qd + li/si);
        float r1 = -rz + (li*rp - rs)/si;
        dz = (r1 - t) * hinv;
        ds = dz - rp;
        dlam = (-rs - li*ds) / si;
        if (ds   < 0.f) cand = fminf(cand, -si/ds);
        if (dlam < 0.f) cand = fminf(cand, -li/dlam);
    }
    float am = blkMin(cand, red);
    float alpha = fminf(1.0f, 0.99f * am);
    float part = 0.f;
    if (tid < NXX) {
        float sn = si + alpha * ds;
        float ln = li + alpha * dlam;
        g_Z [b*NXX + tid] += alpha * dz;
        g_Sl[b*NXX + tid]  = sn;
        g_Lm[b*NXX + tid]  = ln;
        g_Qt[b*NXX + tid] += alpha * t;
        part = sn * ln;
    }
    if (tid < NEQX) g_NU[b*NEQX + tid] += alpha * sy[tid];
    float dot = blkSum(part, red);
    if (tid == 0) g_MU[b] = dot * (1.0f / (float)NXX);
}

// ---------------- init rhs ----------------
__global__ void __launch_bounds__(768) k_rhs0(const float* __restrict__ A, const float* __restrict__ bv) {
    int b = blockIdx.x, tid = threadIdx.x;
    __shared__ float su[NXX];
    if (tid < NXX) su[tid] = g_P[b*NXX + tid] * g_Hinv0[tid];
    __syncthreads();
    int w = tid >> 5, lane = tid & 31;
    for (int g = w; g < NEQX/4; g += 24) {
        int j = g * 4;
        const float* A0 = A + (size_t)j*NXX;
        float s0=0.f, s1=0.f, s2=0.f, s3=0.f;
        for (int k = lane; k < NXX; k += 32) {
            float u = su[k];
            s0 += A0[k]         * u;
            s1 += A0[NXX + k]   * u;
            s2 += A0[2*NXX + k] * u;
            s3 += A0[3*NXX + k] * u;
        }
        #pragma unroll
        for (int o = 16; o; o >>= 1) {
            s0 += __shfl_xor_sync(0xffffffffu, s0, o);
            s1 += __shfl_xor_sync(0xffffffffu, s1, o);
            s2 += __shfl_xor_sync(0xffffffffu, s2, o);
            s3 += __shfl_xor_sync(0xffffffffu, s3, o);
        }
        if (lane == 0) {
            g_RHS[b*NEQX + j]     = -s0 - bv[j];
            g_RHS[b*NEQX + j + 1] = -s1 - bv[j+1];
            g_RHS[b*NEQX + j + 2] = -s2 - bv[j+2];
            g_RHS[b*NEQX + j + 3] = -s3 - bv[j+3];
        }
    }
}

// ---------------- init z, s, lam, q (+ mu) ----------------
__global__ void __launch_bounds__(768) k_initz(const float* __restrict__ A, const float* __restrict__ h) {
    int b = blockIdx.x, tid = threadIdx.x;
    __shared__ float snu[NEQX];
    __shared__ float red[32];
    if (tid < NEQX) snu[tid] = g_NU[b*NEQX + tid];
    __syncthreads();
    float part = 0.f;
    if (tid < NXX) {
        float q = 0.f;
        #pragma unroll 8
        for (int j = 0; j < NEQX; j++) q += A[j*NXX + tid] * snu[j];
        float z = (-g_P[b*NXX + tid] - q) * g_Hinv0[tid];
        float s = fmaxf(h[tid] + z, 1.0f);
        g_Qt[b*NXX + tid] = q;
        g_Z [b*NXX + tid] = z;
        g_Sl[b*NXX + tid] = s;
        g_Lm[b*NXX + tid] = 1.0f;
        part = s;
    }
    float dot = blkSum(part, red);
    if (tid == 0) g_MU[b] = dot * (1.0f / (float)NXX);
}

// ---------------- output copy ----------------
__global__ void k_out(float* __restrict__ out) {
    int b = blockIdx.x, i = threadIdx.x;
    if (i < NXX) out[b*NXX + i] = g_Z[b*NXX + i];
}

// ---------------- launch ----------------
extern "C" void kernel_launch(void* const* d_in, const int* in_sizes, int n_in,
                              void* d_out, int out_size) {
    const float* puzzles = (const float*)d_in[0];
    const float* Q       = (const float*)d_in[1];
    const float* h       = (const float*)d_in[3];
    const float* A       = (const float*)d_in[4];
    const float* bvec    = (const float*)d_in[5];
    float* out = (float*)d_out;

    // init
    k_setup  <<<BAT, 768>>>(puzzles, Q);
    k_syrk   <<<dim3(15, 1), 256>>>(A, bvec, h, 1);
    k_chol   <<<CLW, 256>>>(1);
    k_rhs0   <<<BAT, 768>>>(A, bvec);
    k_trsolve<<<BAT, 320>>>(1);
    k_initz  <<<BAT, 768>>>(A, h);

    // 10 PDIPM iterations (3 kernels each; k_res folded into syrk diag tiles)
    for (int it = 0; it < 10; it++) {
        k_syrk     <<<dim3(15, BAT), 256>>>(A, bvec, h, 0);
        k_chol     <<<BAT*CLW, 256>>>(0);
        k_stepsolve<<<BAT, 768>>>(A, h);
    }
    k_out<<<BAT, 768>>>(out);
}

// round 16
// speedup vs baseline: 1.0577x; 1.0577x over previous
#include <cuda_runtime.h>
#include <cuda_bf16.h>
#include <math.h>

// Problem constants
#define NXX   729
#define NEQX  300
#define BAT   16
#define LDSM  320                 // rows line-aligned: 320*4B = 10 x 128B lines
#define SSTR  (NEQX*LDSM)
#define NPAN  10
#define NB    10
#define CLW   5                   // blocks paired (crank, 9-crank): balanced tiles
#define SIGC  0.1f
#define BIGV  1e9f

// ---------------- device scratch ----------------
__device__ float g_P   [BAT*NXX];
__device__ float g_Z   [BAT*NXX];
__device__ float g_Sl  [BAT*NXX];
__device__ float g_Lm  [BAT*NXX];
__device__ float g_Qt  [BAT*NXX];
__device__ float g_HINV[BAT*NXX];
__device__ float g_R1  [BAT*NXX];
__device__ float g_RP  [BAT*NXX];
__device__ float g_RS  [BAT*NXX];
__device__ float g_NU  [BAT*NEQX];
__device__ float g_RHS [BAT*NEQX];
__device__ float g_Smat[BAT*SSTR];
__device__ float g_S0  [SSTR];
__device__ float g_Minv[BAT*NPAN*1024];
__device__ float g_Minv0[NPAN*1024];
__device__ float g_Qd  [NXX];
__device__ float g_Hinv0[NXX];
__device__ float g_MU  [BAT];

__device__ __forceinline__ void cluster_sync_() {
    asm volatile("barrier.cluster.arrive.aligned;" ::: "memory");
    asm volatile("barrier.cluster.wait.aligned;" ::: "memory");
}

// ---------------- reductions ----------------
__device__ __forceinline__ float blkSum(float v, float* red) {
    #pragma unroll
    for (int o = 16; o; o >>= 1) v += __shfl_xor_sync(0xffffffffu, v, o);
    int w = threadIdx.x >> 5;
    if ((threadIdx.x & 31) == 0) red[w] = v;
    __syncthreads();
    if (threadIdx.x < 32) {
        int nw = blockDim.x >> 5;
        v = (threadIdx.x < nw) ? red[threadIdx.x] : 0.f;
        #pragma unroll
        for (int o = 16; o; o >>= 1) v += __shfl_xor_sync(0xffffffffu, v, o);
        if (threadIdx.x == 0) red[0] = v;
    }
    __syncthreads();
    return red[0];
}

__device__ __forceinline__ float blkMin(float v, float* red) {
    #pragma unroll
    for (int o = 16; o; o >>= 1) v = fminf(v, __shfl_xor_sync(0xffffffffu, v, o));
    int w = threadIdx.x >> 5;
    if ((threadIdx.x & 31) == 0) red[w] = v;
    __syncthreads();
    if (threadIdx.x < 32) {
        int nw = blockDim.x >> 5;
        v = (threadIdx.x < nw) ? red[threadIdx.x] : BIGV;
        #pragma unroll
        for (int o = 16; o; o >>= 1) v = fminf(v, __shfl_xor_sync(0xffffffffu, v, o));
        if (threadIdx.x == 0) red[0] = v;
    }
    __syncthreads();
    return red[0];
}

// ---------------- setup ----------------
__global__ void k_setup(const float* __restrict__ puz, const float* __restrict__ Q) {
    int b = blockIdx.x, i = threadIdx.x;
    if (i < NXX) {
        g_P[b*NXX + i] = -puz[b*NXX + i];
        if (b == 0) {
            float qd = Q[i*NXX + i];
            g_Qd[i] = qd;
            g_Hinv0[i] = 1.0f / qd;
        }
    }
}

// ---------------- batched SYRK: S = A diag(Hinv) A^T (lower triangle) ------
__global__ void __launch_bounds__(256) k_syrk(const float* __restrict__ A, int init) {
    int t = blockIdx.x, b = blockIdx.y;
    int ti = 0;
    while ((ti + 1) * (ti + 2) / 2 <= t) ti++;
    int tj = t - ti * (ti + 1) / 2;
    const float* hv = init ? g_Hinv0 : (g_HINV + b*NXX);
    float* Sout     = init ? g_S0    : (g_Smat + b*SSTR);

    __shared__ __align__(16) float As[32*68];
    __shared__ __align__(16) float Bs[32*68];

    int tid = threadIdx.x;
    int tx = tid & 15, ty = tid >> 4;
    float acc[4][4];
    #pragma unroll
    for (int u = 0; u < 4; u++)
        #pragma unroll
        for (int v = 0; v < 4; v++) acc[u][v] = 0.f;

    int row0 = ti * 64, col0 = tj * 64;
    int cld = tid & 31, rbase = tid >> 5;

    for (int k0 = 0; k0 < NXX; k0 += 32) {
        int k = k0 + cld;
        bool kok = (k < NXX);
        float hval = kok ? hv[k] : 0.f;
        #pragma unroll
        for (int l = 0; l < 8; l++) {
            int r = rbase + l * 8;
            int gi = row0 + r;
            int gj = col0 + r;
            float av = (kok && gi < NEQX) ? A[gi*NXX + k] : 0.f;
            float bv = (kok && gj < NEQX) ? A[gj*NXX + k] : 0.f;
            As[cld*68 + r] = av * hval;
            Bs[cld*68 + r] = bv;
        }
        __syncthreads();
        #pragma unroll
        for (int kk = 0; kk < 32; kk++) {
            float4 a4 = *reinterpret_cast<const float4*>(&As[kk*68 + (ty << 2)]);
            float4 b4 = *reinterpret_cast<const float4*>(&Bs[kk*68 + (tx << 2)]);
            float av[4] = {a4.x, a4.y, a4.z, a4.w};
            float bv[4] = {b4.x, b4.y, b4.z, b4.w};
            #pragma unroll
            for (int u = 0; u < 4; u++)
                #pragma unroll
                for (int v = 0; v < 4; v++) acc[u][v] += av[u] * bv[v];
        }
        __syncthreads();
    }
    #pragma unroll
    for (int u = 0; u < 4; u++) {
        int gi = row0 + (ty << 2) + u;
        #pragma unroll
        for (int v = 0; v < 4; v++) {
            int gj = col0 + (tx << 2) + v;
            if (gi < NEQX && gj < NEQX && gj <= gi)
                Sout[gi*LDSM + gj] = acc[u][v];
        }
    }
}

// ---------------- cluster-parallel right-looking Cholesky ------------------
// Balanced block pairing: rank r owns blocks {r, 9-r} -> equal tile counts
// in phase E (9 tiles per rank at p=0 vs 13 worst-case with r, r+5).
__device__ __forceinline__ int blk_of(int crank, int s) {
    return (s == 0) ? crank : (NB - 1 - crank);
}
__device__ __forceinline__ int owner_of(int p) {
    return (p < CLW) ? p : (NB - 1 - p);
}

__global__ void __launch_bounds__(256) __cluster_dims__(CLW, 1, 1)
k_chol(int init) {
    int batch = blockIdx.x / CLW;
    unsigned crank;
    asm("mov.u32 %0, %%cluster_ctarank;" : "=r"(crank));
    float* S    = init ? g_S0    : (g_Smat + batch*SSTR);
    float* Minv = init ? g_Minv0 : (g_Minv + batch*(NPAN*1024));
    int tid = threadIdx.x;
    int lane = tid & 31;
    int wid = tid >> 5;

    __shared__ float ld[32*33];
    __shared__ float mi[32*33];
    __shared__ float tT[16*17];
    __shared__ float sinvd[32];
    __shared__ float pan[64*33];   // own 2 blocks: staged B, then X

    for (int p = 0; p < NPAN; p++) {
        int col0 = p * 32;
        int pw = NEQX - col0; if (pw > 32) pw = 32;
        int owner = owner_of(p);

        cluster_sync_();   // prior trailing updates visible everywhere

        // ---- phase A: warp0 factors diag (redundant on all CTAs);
        //      warps 1..7 stage own sub-panel rows (coalesced)
        if (wid == 0) {
            float row[32];
            #pragma unroll
            for (int j = 0; j < 32; j++)
                row[j] = (lane < pw && j < pw) ? S[(col0+lane)*LDSM + col0 + j] : 0.f;
            float sinv = 0.f;
            #pragma unroll
            for (int c = 0; c < 32; c++) {
                if (c < pw) {
                    float piv = __shfl_sync(0xffffffffu, row[c], c);
                    float inv = rsqrtf(piv);
                    float d   = piv * inv;
                    float lrc;
                    if (lane == c)      lrc = d;
                    else if (lane > c)  lrc = row[c] * inv;
                    else                lrc = 0.f;
                    row[c] = lrc;
                    if (lane == c) sinv = 1.0f / d;
                    #pragma unroll
                    for (int j = 0; j < 32; j++) {
                        if (j > c) {
                            float ljc = __shfl_sync(0xffffffffu, lrc, j);
                            row[j] -= lrc * ljc;
                        }
                    }
                }
            }
            sinvd[lane] = sinv;
            #pragma unroll
            for (int j = 0; j < 32; j++) ld[lane*33 + j] = row[j];
            if ((int)crank == owner && lane < pw) {
                #pragma unroll
                for (int j = 0; j < 32; j++)
                    S[(col0+lane)*LDSM + col0 + j] = row[j];
            }
        } else {
            #pragma unroll
            for (int s = 0; s < 2; s++) {
                int bi = blk_of(crank, s);
                if (bi <= p) continue;
                int nr = NEQX - bi*32; if (nr > 32) nr = 32;
                for (int idx = tid - 32; idx < 1024; idx += 224) {
                    int r = idx >> 5, c = idx & 31;
                    pan[(s*32+r)*33 + c] = (r < nr && c < pw)
                        ? S[(bi*32+r)*LDSM + col0 + c] : 0.f;
                }
            }
        }
        __syncthreads();

        // ---- phase B: block-split Minv = [[M11,0],[-M22*L21*M11, M22]] ----
        if (wid == 0) {
            int c = lane & 15;
            int half = lane >> 4;
            int base = half << 4;
            float xc[16];
            #pragma unroll
            for (int j = 0; j < 16; j++) xc[j] = 0.f;
            xc[c] = sinvd[base + c];
            #pragma unroll
            for (int rr = 1; rr < 16; rr++) {
                float s = 0.f;
                #pragma unroll
                for (int j = 0; j < 16; j++)
                    if (j < rr) s += ld[(base+rr)*33 + base + j] * xc[j];
                if (rr > c) xc[rr] = -s * sinvd[base + rr];
            }
            #pragma unroll
            for (int rr = 0; rr < 16; rr++) {
                mi[(base+rr)*33 + base + c] = xc[rr];
                if (half == 0) mi[rr*33 + 16 + c] = 0.f;
            }
            __syncwarp();
            // T = L21 * M11
            {
                int cc = lane & 15;
                int r0 = (lane >> 4) * 8;
                #pragma unroll
                for (int r = 0; r < 8; r++) {
                    float s = 0.f;
                    #pragma unroll
                    for (int j = 0; j < 16; j++)
                        s += ld[(16 + r0 + r)*33 + j] * mi[j*33 + cc];
                    tT[(r0 + r)*17 + cc] = s;
                }
            }
            __syncwarp();
            // M21 = -M22 * T
            {
                int cc = lane & 15;
                int r0 = (lane >> 4) * 8;
                #pragma unroll
                for (int r = 0; r < 8; r++) {
                    float s = 0.f;
                    #pragma unroll
                    for (int j = 0; j < 16; j++)
                        s += mi[(16 + r0 + r)*33 + 16 + j] * tT[j*17 + cc];
                    mi[(16 + r0 + r)*33 + cc] = -s;
                }
            }
            __syncwarp();
            if ((int)crank == owner) {
                float* Mp = Minv + p * 1024;
                #pragma unroll
                for (int rr = 0; rr < 32; rr++)
                    Mp[rr*32 + lane] = mi[rr*33 + lane];
            }
        }
        __syncthreads();

        // ---- phase C: panel solve as GEMM  X = B * Minv^T ----
        #pragma unroll
        for (int s = 0; s < 2; s++) {
            int bi = blk_of(crank, s);
            if (bi <= p) continue;
            int r  = tid >> 3;
            int c0 = (tid & 7) << 2;
            float breg[32];
            #pragma unroll
            for (int j = 0; j < 32; j++) breg[j] = pan[(s*32+r)*33 + j];
            float a0=0.f, a1=0.f, a2=0.f, a3=0.f;
            #pragma unroll
            for (int j = 0; j < 32; j++) {
                float bj = breg[j];
                a0 += bj * mi[(c0+0)*33 + j];
                a1 += bj * mi[(c0+1)*33 + j];
                a2 += bj * mi[(c0+2)*33 + j];
                a3 += bj * mi[(c0+3)*33 + j];
            }
            __syncwarp();
            pan[(s*32+r)*33 + c0 + 0] = a0;
            pan[(s*32+r)*33 + c0 + 1] = a1;
            pan[(s*32+r)*33 + c0 + 2] = a2;
            pan[(s*32+r)*33 + c0 + 3] = a3;
        }
        __syncthreads();

        // ---- phase D: write X to gmem, lower + mirror (both coalesced) ----
        #pragma unroll
        for (int s = 0; s < 2; s++) {
            int bi = blk_of(crank, s);
            if (bi <= p) continue;
            int nr = NEQX - bi*32; if (nr > 32) nr = 32;
            for (int idx = tid; idx < 1024; idx += 256) {
                int r = idx >> 5, c = idx & 31;
                if (r < nr && c < pw)
                    S[(bi*32+r)*LDSM + col0 + c] = pan[(s*32+r)*33 + c];
            }
            for (int idx = tid; idx < 1024; idx += 256) {
                int c = idx >> 5, r = idx & 31;
                if (r < nr && c < pw)
                    S[(col0+c)*LDSM + bi*32 + r] = pan[(s*32+r)*33 + c];
            }
        }
        cluster_sync_();

        // ---- phase E: trailing update, one tile per warp, NO CTA syncs ----
        {
            int tcount = 0;
            #pragma unroll
            for (int s = 0; s < 2; s++) {
                int bi = blk_of(crank, s);
                if (bi <= p) continue;
                int nri = NEQX - bi*32; if (nri > 32) nri = 32;
                for (int jb = p + 1; jb <= bi; jb++) {
                    if ((tcount++ & 7) != wid) continue;
                    int nrj = NEQX - jb*32; if (nrj > 32) nrj = 32;
                    bool cok = (lane < nrj);
                    float xjr[32];   // X_jb[lane][k] from mirror rows (coalesced)
                    #pragma unroll
                    for (int k = 0; k < 32; k++)
                        xjr[k] = cok ? S[(col0+k)*LDSM + jb*32 + lane] : 0.f;
                    for (int r = 0; r < nri; r++) {
                        float acc = 0.f;
                        #pragma unroll
                        for (int k = 0; k < 32; k++)
                            acc += pan[(s*32+r)*33 + k] * xjr[k];
                        if (cok)
                            S[(size_t)(bi*32+r)*LDSM + jb*32 + lane] -= acc;
                    }
                }
            }
        }
    }
}

// ---------------- standalone triangular solve (init only) -----------------
__global__ void __launch_bounds__(320) k_trsolve(int init) {
    int b = blockIdx.x;
    const float* S    = init ? g_S0    : (g_Smat + b*SSTR);
    const float* Minv = init ? g_Minv0 : (g_Minv + b*(NPAN*1024));
    const float* rhs  = g_RHS + b*NEQX;
    float* out        = g_NU + b*NEQX;
    __shared__ float sy[320];
    __shared__ float mv[32*33];
    int tid = threadIdx.x;
    int lane = tid & 31;
    sy[tid] = (tid < NEQX) ? rhs[tid] : 0.f;
    __syncthreads();
    for (int p = 0; p < NPAN; p++) {
        int col0 = p * 32;
        int pw = NEQX - col0; if (pw > 32) pw = 32;
        const float* Mp = Minv + p * 1024;
        for (int idx = tid; idx < 1024; idx += 320) {
            int i = idx >> 5, j = idx & 31;
            mv[i*33 + j] = Mp[i*32 + j];
        }
        __syncthreads();
        if (tid < 32) {
            float y = 0.f;
            #pragma unroll 8
            for (int j = 0; j < 32; j++) y += mv[lane*33 + j] * sy[col0 + j];
            __syncwarp();
            if (lane < pw) sy[col0 + lane] = y;
        }
        __syncthreads();
        int rem = NEQX - col0 - pw;
        if (tid < rem) {
            int i = col0 + pw + tid;
            float s = 0.f;
            #pragma unroll 8
            for (int c = 0; c < 32; c++)
                if (c < pw) s += S[(col0 + c)*LDSM + i] * sy[col0 + c];
            sy[i] -= s;
        }
        __syncthreads();
    }
    for (int p = NPAN - 1; p >= 0; p--) {
        int col0 = p * 32;
        int pw = NEQX - col0; if (pw > 32) pw = 32;
        const float* Mp = Minv + p * 1024;
        for (int idx = tid; idx < 1024; idx += 320) {
            int i = idx >> 5, j = idx & 31;
            mv[i*33 + j] = Mp[i*32 + j];
        }
        __syncthreads();
        if (tid < 32) {
            float x = 0.f;
            #pragma unroll 8
            for (int j = 0; j < 32; j++) x += mv[j*33 + lane] * sy[col0 + j];
            __syncwarp();
            if (lane < pw) sy[col0 + lane] = x;
        }
        __syncthreads();
        if (tid < col0) {
            float s = 0.f;
            #pragma unroll 8
            for (int c = 0; c < 32; c++)
                if (c < pw) s += S[(col0 + c)*LDSM + tid] * sy[col0 + c];
            sy[tid] -= s;
        }
        __syncthreads();
    }
    if (tid < NEQX) out[tid] = sy[tid];
}

// ---------------- fused trsolve + step (+ mu); ALL Minv panels resident ----
__global__ void __launch_bounds__(768) k_stepsolve(const float* __restrict__ A) {
    int b = blockIdx.x, tid = threadIdx.x, lane = tid & 31;
    const float* S    = g_Smat + b*SSTR;
    const float* Minv = g_Minv + b*(NPAN*1024);
    __shared__ float sy[320];
    __shared__ float miAll[NPAN*32*33];   // 42.2 KB: all 10 panel inverses
    __shared__ float red[32];
    if (tid < 320) sy[tid] = (tid < NEQX) ? g_RHS[b*NEQX + tid] : 0.f;
    for (int idx = tid; idx < NPAN*1024; idx += 768) {
        int p = idx >> 10;
        int e = idx & 1023;
        miAll[p*(32*33) + (e >> 5)*33 + (e & 31)] = Minv[idx];
    }
    __syncthreads();

    // forward: L y = rhs
    for (int p = 0; p < NPAN; p++) {
        int col0 = p * 32;
        int pw = NEQX - col0; if (pw > 32) pw = 32;
        const float* mv = miAll + p*(32*33);
        if (tid < 32) {
            float y = 0.f;
            #pragma unroll 8
            for (int j = 0; j < 32; j++) y += mv[lane*33 + j] * sy[col0 + j];
            __syncwarp();
            if (lane < pw) sy[col0 + lane] = y;
        }
        __syncthreads();
        int rem = NEQX - col0 - pw;
        if (tid < rem) {
            int i = col0 + pw + tid;
            float s = 0.f;
            #pragma unroll 8
            for (int c = 0; c < 32; c++)
                if (c < pw) s += S[(col0 + c)*LDSM + i] * sy[col0 + c];
            sy[i] -= s;
        }
        __syncthreads();
    }
    // backward: L^T x = y
    for (int p = NPAN - 1; p >= 0; p--) {
        int col0 = p * 32;
        int pw = NEQX - col0; if (pw > 32) pw = 32;
        const float* mv = miAll + p*(32*33);
        if (tid < 32) {
            float x = 0.f;
            #pragma unroll 8
            for (int j = 0; j < 32; j++) x += mv[j*33 + lane] * sy[col0 + j];
            __syncwarp();
            if (lane < pw) sy[col0 + lane] = x;
        }
        __syncthreads();
        if (tid < col0) {
            float s = 0.f;
            #pragma unroll 8
            for (int c = 0; c < 32; c++)
                if (c < pw) s += S[(col0 + c)*LDSM + tid] * sy[col0 + c];
            sy[tid] -= s;
        }
        __syncthreads();
    }
    // sy now holds dnu

    // step phase
    float cand = BIGV;
    float t = 0.f, dz = 0.f, ds = 0.f, dlam = 0.f, si = 0.f, li = 0.f;
    if (tid < NXX) {
        #pragma unroll 8
        for (int j = 0; j < NEQX; j++) t += A[j*NXX + tid] * sy[j];
        float r1   = g_R1 [b*NXX + tid];
        float hinv = g_HINV[b*NXX + tid];
        float rp   = g_RP [b*NXX + tid];
        float rs   = g_RS [b*NXX + tid];
        si = g_Sl[b*NXX + tid];
        li = g_Lm[b*NXX + tid];
        dz = (r1 - t) * hinv;
        ds = dz - rp;
        dlam = (-rs - li*ds) / si;
        if (ds   < 0.f) cand = fminf(cand, -si/ds);
        if (dlam < 0.f) cand = fminf(cand, -li/dlam);
    }
    float am = blkMin(cand, red);
    float alpha = fminf(1.0f, 0.99f * am);
    float part = 0.f;
    if (tid < NXX) {
        float sn = si + alpha * ds;
        float ln = li + alpha * dlam;
        g_Z [b*NXX + tid] += alpha * dz;
        g_Sl[b*NXX + tid]  = sn;
        g_Lm[b*NXX + tid]  = ln;
        g_Qt[b*NXX + tid] += alpha * t;
        part = sn * ln;
    }
    if (tid < NEQX) g_NU[b*NEQX + tid] += alpha * sy[tid];
    float dot = blkSum(part, red);
    if (tid == 0) g_MU[b] = dot * (1.0f / (float)NXX);
}

// ---------------- init rhs ----------------
__global__ void __launch_bounds__(768) k_rhs0(const float* __restrict__ A, const float* __restrict__ bv) {
    int b = blockIdx.x, tid = threadIdx.x;
    __shared__ float su[NXX];
    if (tid < NXX) su[tid] = g_P[b*NXX + tid] * g_Hinv0[tid];
    __syncthreads();
    int w = tid >> 5, lane = tid & 31;
    for (int g = w; g < NEQX/4; g += 24) {
        int j = g * 4;
        const float* A0 = A + (size_t)j*NXX;
        float s0=0.f, s1=0.f, s2=0.f, s3=0.f;
        for (int k = lane; k < NXX; k += 32) {
            float u = su[k];
            s0 += A0[k]         * u;
            s1 += A0[NXX + k]   * u;
            s2 += A0[2*NXX + k] * u;
            s3 += A0[3*NXX + k] * u;
        }
        #pragma unroll
        for (int o = 16; o; o >>= 1) {
            s0 += __shfl_xor_sync(0xffffffffu, s0, o);
            s1 += __shfl_xor_sync(0xffffffffu, s1, o);
            s2 += __shfl_xor_sync(0xffffffffu, s2, o);
            s3 += __shfl_xor_sync(0xffffffffu, s3, o);
        }
        if (lane == 0) {
            g_RHS[b*NEQX + j]     = -s0 - bv[j];
            g_RHS[b*NEQX + j + 1] = -s1 - bv[j+1];
            g_RHS[b*NEQX + j + 2] = -s2 - bv[j+2];
            g_RHS[b*NEQX + j + 3] = -s3 - bv[j+3];
        }
    }
}

// ---------------- init z, s, lam, q (+ mu) ----------------
__global__ void __launch_bounds__(768) k_initz(const float* __restrict__ A, const float* __restrict__ h) {
    int b = blockIdx.x, tid = threadIdx.x;
    __shared__ float snu[NEQX];
    __shared__ float red[32];
    if (tid < NEQX) snu[tid] = g_NU[b*NEQX + tid];
    __syncthreads();
    float part = 0.f;
    if (tid < NXX) {
        float q = 0.f;
        #pragma unroll 8
        for (int j = 0; j < NEQX; j++) q += A[j*NXX + tid] * snu[j];
        float z = (-g_P[b*NXX + tid] - q) * g_Hinv0[tid];
        float s = fmaxf(h[tid] + z, 1.0f);
        g_Qt[b*NXX + tid] = q;
        g_Z [b*NXX + tid] = z;
        g_Sl[b*NXX + tid] = s;
        g_Lm[b*NXX + tid] = 1.0f;
        part = s;
    }
    float dot = blkSum(part, red);
    if (tid == 0) g_MU[b] = dot * (1.0f / (float)NXX);
}

// ---------------- per-iteration residuals + dnu RHS (wide: 4 CTAs/batch) ---
__global__ void __launch_bounds__(768) k_res(const float* __restrict__ A,
                                             const float* __restrict__ bv,
                                             const float* __restrict__ h) {
    int x = blockIdx.x, b = blockIdx.y, tid = threadIdx.x;
    __shared__ float su[NXX];
    float mu = g_MU[b];
    if (tid < NXX) {
        float si = g_Sl[b*NXX + tid];
        float li = g_Lm[b*NXX + tid];
        float zi = g_Z[b*NXX + tid];
        float pi = g_P[b*NXX + tid];
        float qi = g_Qt[b*NXX + tid];
        float qd = g_Qd[tid];
        float hi = h[tid];
        float rz = qd*zi + pi - li + qi;
        float rp = si - zi - hi;
        float rs = si*li - SIGC*mu;
        float hd = qd + li/si;
        float hinv = 1.0f/hd;
        float r1 = -rz + (li*rp - rs)/si;
        if (x == 0) {
            g_HINV[b*NXX + tid] = hinv;
            g_R1 [b*NXX + tid] = r1;
            g_RP [b*NXX + tid] = rp;
            g_RS [b*NXX + tid] = rs;
        }
        su[tid] = r1*hinv + zi;
    }
    __syncthreads();
    int w = tid >> 5, lane = tid & 31;
    int g = x * 24 + w;                 // 4 CTAs x 24 warps = 96 slots >= 75 groups
    if (g < NEQX/4) {
        int j = g * 4;
        const float* A0 = A + (size_t)j*NXX;
        float s0=0.f, s1=0.f, s2=0.f, s3=0.f;
        for (int k = lane; k < NXX; k += 32) {
            float u = su[k];
            s0 += A0[k]         * u;
            s1 += A0[NXX + k]   * u;
            s2 += A0[2*NXX + k] * u;
            s3 += A0[3*NXX + k] * u;
        }
        #pragma unroll
        for (int o = 16; o; o >>= 1) {
            s0 += __shfl_xor_sync(0xffffffffu, s0, o);
            s1 += __shfl_xor_sync(0xffffffffu, s1, o);
            s2 += __shfl_xor_sync(0xffffffffu, s2, o);
            s3 += __shfl_xor_sync(0xffffffffu, s3, o);
        }
        if (lane == 0) {
            g_RHS[b*NEQX + j]     = s0 - bv[j];
            g_RHS[b*NEQX + j + 1] = s1 - bv[j+1];
            g_RHS[b*NEQX + j + 2] = s2 - bv[j+2];
            g_RHS[b*NEQX + j + 3] = s3 - bv[j+3];
        }
    }
}

// ---------------- output copy ----------------
__global__ void k_out(float* __restrict__ out) {
    int b = blockIdx.x, i = threadIdx.x;
    if (i < NXX) out[b*NXX + i] = g_Z[b*NXX + i];
}

// ---------------- launch ----------------
extern "C" void kernel_launch(void* const* d_in, const int* in_sizes, int n_in,
                              void* d_out, int out_size) {
    const float* puzzles = (const float*)d_in[0];
    const float* Q       = (const float*)d_in[1];
    const float* h       = (const float*)d_in[3];
    const float* A       = (const float*)d_in[4];
    const float* bvec    = (const float*)d_in[5];
    float* out = (float*)d_out;

    // init
    k_setup  <<<BAT, 768>>>(puzzles, Q);
    k_syrk   <<<dim3(15, 1), 256>>>(A, 1);
    k_chol   <<<CLW, 256>>>(1);
    k_rhs0   <<<BAT, 768>>>(A, bvec);
    k_trsolve<<<BAT, 320>>>(1);
    k_initz  <<<BAT, 768>>>(A, h);

    // 10 PDIPM iterations
    for (int it = 0; it < 10; it++) {
        k_res      <<<dim3(4, BAT), 768>>>(A, bvec, h);
        k_syrk     <<<dim3(15, BAT), 256>>>(A, 0);
        k_chol     <<<BAT*CLW, 256>>>(0);
        k_stepsolve<<<BAT, 768>>>(A);
    }
    k_out<<<BAT, 768>>>(out);
}

// round 17
// speedup vs baseline: 1.1036x; 1.0434x over previous
#include <cuda_runtime.h>
#include <cuda_bf16.h>
#include <math.h>

// Problem constants
#define NXX   729
#define NEQX  300
#define BAT   16
#define LDSM  320                 // rows line-aligned: 320*4B = 10 x 128B lines
#define SSTR  (NEQX*LDSM)
#define NPAN  10
#define NB    10
#define CLW   5                   // blocks paired (crank, 9-crank): balanced tiles
#define SIGC  0.1f
#define BIGV  1e9f

// ---------------- device scratch ----------------
__device__ float g_P   [BAT*NXX];
__device__ float g_Z   [BAT*NXX];
__device__ float g_Sl  [BAT*NXX];
__device__ float g_Lm  [BAT*NXX];
__device__ float g_Qt  [BAT*NXX];
__device__ float g_HINV[BAT*NXX];
__device__ float g_R1  [BAT*NXX];
__device__ float g_RP  [BAT*NXX];
__device__ float g_RS  [BAT*NXX];
__device__ float g_NU  [BAT*NEQX];
__device__ float g_RHS [BAT*NEQX];
__device__ float g_Smat[BAT*SSTR];
__device__ float g_S0  [SSTR];
__device__ float g_Minv[BAT*NPAN*1024];
__device__ float g_Minv0[NPAN*1024];
__device__ float g_Qd  [NXX];
__device__ float g_Hinv0[NXX];
__device__ float g_MU  [BAT];

__device__ __forceinline__ void cluster_sync_() {
    asm volatile("barrier.cluster.arrive.aligned;" ::: "memory");
    asm volatile("barrier.cluster.wait.aligned;" ::: "memory");
}

// ---------------- reductions ----------------
__device__ __forceinline__ float blkSum(float v, float* red) {
    #pragma unroll
    for (int o = 16; o; o >>= 1) v += __shfl_xor_sync(0xffffffffu, v, o);
    int w = threadIdx.x >> 5;
    if ((threadIdx.x & 31) == 0) red[w] = v;
    __syncthreads();
    if (threadIdx.x < 32) {
        int nw = blockDim.x >> 5;
        v = (threadIdx.x < nw) ? red[threadIdx.x] : 0.f;
        #pragma unroll
        for (int o = 16; o; o >>= 1) v += __shfl_xor_sync(0xffffffffu, v, o);
        if (threadIdx.x == 0) red[0] = v;
    }
    __syncthreads();
    return red[0];
}

__device__ __forceinline__ float blkMin(float v, float* red) {
    #pragma unroll
    for (int o = 16; o; o >>= 1) v = fminf(v, __shfl_xor_sync(0xffffffffu, v, o));
    int w = threadIdx.x >> 5;
    if ((threadIdx.x & 31) == 0) red[w] = v;
    __syncthreads();
    if (threadIdx.x < 32) {
        int nw = blockDim.x >> 5;
        v = (threadIdx.x < nw) ? red[threadIdx.x] : BIGV;
        #pragma unroll
        for (int o = 16; o; o >>= 1) v = fminf(v, __shfl_xor_sync(0xffffffffu, v, o));
        if (threadIdx.x == 0) red[0] = v;
    }
    __syncthreads();
    return red[0];
}

// ---------------- setup ----------------
__global__ void k_setup(const float* __restrict__ puz, const float* __restrict__ Q) {
    int b = blockIdx.x, i = threadIdx.x;
    if (i < NXX) {
        g_P[b*NXX + i] = -puz[b*NXX + i];
        if (b == 0) {
            float qd = Q[i*NXX + i];
            g_Qd[i] = qd;
            g_Hinv0[i] = 1.0f / qd;
        }
    }
}

// ---------------- batched SYRK: S = A diag(Hinv) A^T (lower triangle) ------
__global__ void __launch_bounds__(256) k_syrk(const float* __restrict__ A, int init) {
    int t = blockIdx.x, b = blockIdx.y;
    int ti = 0;
    while ((ti + 1) * (ti + 2) / 2 <= t) ti++;
    int tj = t - ti * (ti + 1) / 2;
    const float* hv = init ? g_Hinv0 : (g_HINV + b*NXX);
    float* Sout     = init ? g_S0    : (g_Smat + b*SSTR);

    __shared__ __align__(16) float As[32*68];
    __shared__ __align__(16) float Bs[32*68];

    int tid = threadIdx.x;
    int tx = tid & 15, ty = tid >> 4;
    float acc[4][4];
    #pragma unroll
    for (int u = 0; u < 4; u++)
        #pragma unroll
        for (int v = 0; v < 4; v++) acc[u][v] = 0.f;

    int row0 = ti * 64, col0 = tj * 64;
    int cld = tid & 31, rbase = tid >> 5;

    for (int k0 = 0; k0 < NXX; k0 += 32) {
        int k = k0 + cld;
        bool kok = (k < NXX);
        float hval = kok ? hv[k] : 0.f;
        #pragma unroll
        for (int l = 0; l < 8; l++) {
            int r = rbase + l * 8;
            int gi = row0 + r;
            int gj = col0 + r;
            float av = (kok && gi < NEQX) ? A[gi*NXX + k] : 0.f;
            float bv = (kok && gj < NEQX) ? A[gj*NXX + k] : 0.f;
            As[cld*68 + r] = av * hval;
            Bs[cld*68 + r] = bv;
        }
        __syncthreads();
        #pragma unroll
        for (int kk = 0; kk < 32; kk++) {
            float4 a4 = *reinterpret_cast<const float4*>(&As[kk*68 + (ty << 2)]);
            float4 b4 = *reinterpret_cast<const float4*>(&Bs[kk*68 + (tx << 2)]);
            float av[4] = {a4.x, a4.y, a4.z, a4.w};
            float bv[4] = {b4.x, b4.y, b4.z, b4.w};
            #pragma unroll
            for (int u = 0; u < 4; u++)
                #pragma unroll
                for (int v = 0; v < 4; v++) acc[u][v] += av[u] * bv[v];
        }
        __syncthreads();
    }
    #pragma unroll
    for (int u = 0; u < 4; u++) {
        int gi = row0 + (ty << 2) + u;
        #pragma unroll
        for (int v = 0; v < 4; v++) {
            int gj = col0 + (tx << 2) + v;
            if (gi < NEQX && gj < NEQX && gj <= gi)
                Sout[gi*LDSM + gj] = acc[u][v];
        }
    }
}

// ---------------- cluster-parallel right-looking Cholesky ------------------
// Balanced block pairing: rank r owns blocks {r, 9-r}. Phase E uses 16-row
// HALF-TILE warp tasks: 18 tasks over 8 warps at p=0 -> max 3 (48 rows) vs
// 2 full tiles (64 rows) before.
__device__ __forceinline__ int blk_of(int crank, int s) {
    return (s == 0) ? crank : (NB - 1 - crank);
}
__device__ __forceinline__ int owner_of(int p) {
    return (p < CLW) ? p : (NB - 1 - p);
}

__global__ void __launch_bounds__(256) __cluster_dims__(CLW, 1, 1)
k_chol(int init) {
    int batch = blockIdx.x / CLW;
    unsigned crank;
    asm("mov.u32 %0, %%cluster_ctarank;" : "=r"(crank));
    float* S    = init ? g_S0    : (g_Smat + batch*SSTR);
    float* Minv = init ? g_Minv0 : (g_Minv + batch*(NPAN*1024));
    int tid = threadIdx.x;
    int lane = tid & 31;
    int wid = tid >> 5;

    __shared__ float ld[32*33];
    __shared__ float mi[32*33];
    __shared__ float tT[16*17];
    __shared__ float sinvd[32];
    __shared__ float pan[64*33];   // own 2 blocks: staged B, then X

    for (int p = 0; p < NPAN; p++) {
        int col0 = p * 32;
        int pw = NEQX - col0; if (pw > 32) pw = 32;
        int owner = owner_of(p);

        cluster_sync_();   // prior trailing updates visible everywhere

        // ---- phase A: warp0 factors diag (redundant on all CTAs);
        //      warps 1..7 stage own sub-panel rows (coalesced)
        if (wid == 0) {
            float row[32];
            #pragma unroll
            for (int j = 0; j < 32; j++)
                row[j] = (lane < pw && j < pw) ? S[(col0+lane)*LDSM + col0 + j] : 0.f;
            float sinv = 0.f;
            #pragma unroll
            for (int c = 0; c < 32; c++) {
                if (c < pw) {
                    float piv = __shfl_sync(0xffffffffu, row[c], c);
                    float inv = rsqrtf(piv);
                    float d   = piv * inv;
                    float lrc;
                    if (lane == c)      lrc = d;
                    else if (lane > c)  lrc = row[c] * inv;
                    else                lrc = 0.f;
                    row[c] = lrc;
                    if (lane == c) sinv = 1.0f / d;
                    #pragma unroll
                    for (int j = 0; j < 32; j++) {
                        if (j > c) {
                            float ljc = __shfl_sync(0xffffffffu, lrc, j);
                            row[j] -= lrc * ljc;
                        }
                    }
                }
            }
            sinvd[lane] = sinv;
            #pragma unroll
            for (int j = 0; j < 32; j++) ld[lane*33 + j] = row[j];
            if ((int)crank == owner && lane < pw) {
                #pragma unroll
                for (int j = 0; j < 32; j++)
                    S[(col0+lane)*LDSM + col0 + j] = row[j];
            }
        } else {
            #pragma unroll
            for (int s = 0; s < 2; s++) {
                int bi = blk_of(crank, s);
                if (bi <= p) continue;
                int nr = NEQX - bi*32; if (nr > 32) nr = 32;
                for (int idx = tid - 32; idx < 1024; idx += 224) {
                    int r = idx >> 5, c = idx & 31;
                    pan[(s*32+r)*33 + c] = (r < nr && c < pw)
                        ? S[(bi*32+r)*LDSM + col0 + c] : 0.f;
                }
            }
        }
        __syncthreads();

        // ---- phase B: block-split Minv = [[M11,0],[-M22*L21*M11, M22]] ----
        if (wid == 0) {
            int c = lane & 15;
            int half = lane >> 4;
            int base = half << 4;
            float xc[16];
            #pragma unroll
            for (int j = 0; j < 16; j++) xc[j] = 0.f;
            xc[c] = sinvd[base + c];
            #pragma unroll
            for (int rr = 1; rr < 16; rr++) {
                float s = 0.f;
                #pragma unroll
                for (int j = 0; j < 16; j++)
                    if (j < rr) s += ld[(base+rr)*33 + base + j] * xc[j];
                if (rr > c) xc[rr] = -s * sinvd[base + rr];
            }
            #pragma unroll
            for (int rr = 0; rr < 16; rr++) {
                mi[(base+rr)*33 + base + c] = xc[rr];
                if (half == 0) mi[rr*33 + 16 + c] = 0.f;
            }
            __syncwarp();
            // T = L21 * M11
            {
                int cc = lane & 15;
                int r0 = (lane >> 4) * 8;
                #pragma unroll
                for (int r = 0; r < 8; r++) {
                    float s = 0.f;
                    #pragma unroll
                    for (int j = 0; j < 16; j++)
                        s += ld[(16 + r0 + r)*33 + j] * mi[j*33 + cc];
                    tT[(r0 + r)*17 + cc] = s;
                }
            }
            __syncwarp();
            // M21 = -M22 * T
            {
                int cc = lane & 15;
                int r0 = (lane >> 4) * 8;
                #pragma unroll
                for (int r = 0; r < 8; r++) {
                    float s = 0.f;
                    #pragma unroll
                    for (int j = 0; j < 16; j++)
                        s += mi[(16 + r0 + r)*33 + 16 + j] * tT[j*17 + cc];
                    mi[(16 + r0 + r)*33 + cc] = -s;
                }
            }
            __syncwarp();
            if ((int)crank == owner) {
                float* Mp = Minv + p * 1024;
                #pragma unroll
                for (int rr = 0; rr < 32; rr++)
                    Mp[rr*32 + lane] = mi[rr*33 + lane];
            }
        }
        __syncthreads();

        // ---- phase C: panel solve as GEMM  X = B * Minv^T ----
        #pragma unroll
        for (int s = 0; s < 2; s++) {
            int bi = blk_of(crank, s);
            if (bi <= p) continue;
            int r  = tid >> 3;
            int c0 = (tid & 7) << 2;
            float breg[32];
            #pragma unroll
            for (int j = 0; j < 32; j++) breg[j] = pan[(s*32+r)*33 + j];
            float a0=0.f, a1=0.f, a2=0.f, a3=0.f;
            #pragma unroll
            for (int j = 0; j < 32; j++) {
                float bj = breg[j];
                a0 += bj * mi[(c0+0)*33 + j];
                a1 += bj * mi[(c0+1)*33 + j];
                a2 += bj * mi[(c0+2)*33 + j];
                a3 += bj * mi[(c0+3)*33 + j];
            }
            __syncwarp();
            pan[(s*32+r)*33 + c0 + 0] = a0;
            pan[(s*32+r)*33 + c0 + 1] = a1;
            pan[(s*32+r)*33 + c0 + 2] = a2;
            pan[(s*32+r)*33 + c0 + 3] = a3;
        }
        __syncthreads();

        // ---- phase D: write X to gmem, lower + mirror (both coalesced) ----
        #pragma unroll
        for (int s = 0; s < 2; s++) {
            int bi = blk_of(crank, s);
            if (bi <= p) continue;
            int nr = NEQX - bi*32; if (nr > 32) nr = 32;
            for (int idx = tid; idx < 1024; idx += 256) {
                int r = idx >> 5, c = idx & 31;
                if (r < nr && c < pw)
                    S[(bi*32+r)*LDSM + col0 + c] = pan[(s*32+r)*33 + c];
            }
            for (int idx = tid; idx < 1024; idx += 256) {
                int c = idx >> 5, r = idx & 31;
                if (r < nr && c < pw)
                    S[(col0+c)*LDSM + bi*32 + r] = pan[(s*32+r)*33 + c];
            }
        }
        cluster_sync_();

        // ---- phase E: trailing update, one 16-row HALF-TILE per warp ------
        {
            int tcount = 0;
            #pragma unroll
            for (int s = 0; s < 2; s++) {
                int bi = blk_of(crank, s);
                if (bi <= p) continue;
                int nri = NEQX - bi*32; if (nri > 32) nri = 32;
                for (int jb = p + 1; jb <= bi; jb++) {
                    int nrj = NEQX - jb*32; if (nrj > 32) nrj = 32;
                    #pragma unroll
                    for (int hh = 0; hh < 2; hh++) {
                        if ((tcount++ & 7) != wid) continue;
                        int rlo = hh * 16;
                        int rhi = rlo + 16; if (rhi > nri) rhi = nri;
                        if (rlo >= nri) continue;
                        bool cok = (lane < nrj);
                        float xjr[32];   // X_jb[lane][k] from mirror rows
                        #pragma unroll
                        for (int k = 0; k < 32; k++)
                            xjr[k] = cok ? S[(col0+k)*LDSM + jb*32 + lane] : 0.f;
                        for (int r = rlo; r < rhi; r++) {
                            float acc = 0.f;
                            #pragma unroll
                            for (int k = 0; k < 32; k++)
                                acc += pan[(s*32+r)*33 + k] * xjr[k];
                            if (cok)
                                S[(size_t)(bi*32+r)*LDSM + jb*32 + lane] -= acc;
                        }
                    }
                }
            }
        }
    }
}

// ---------------- standalone triangular solve (init only) -----------------
__global__ void __launch_bounds__(320) k_trsolve(int init) {
    int b = blockIdx.x;
    const float* S    = init ? g_S0    : (g_Smat + b*SSTR);
    const float* Minv = init ? g_Minv0 : (g_Minv + b*(NPAN*1024));
    const float* rhs  = g_RHS + b*NEQX;
    float* out        = g_NU + b*NEQX;
    __shared__ float sy[320];
    __shared__ float mv[32*33];
    int tid = threadIdx.x;
    int lane = tid & 31;
    sy[tid] = (tid < NEQX) ? rhs[tid] : 0.f;
    __syncthreads();
    for (int p = 0; p < NPAN; p++) {
        int col0 = p * 32;
        int pw = NEQX - col0; if (pw > 32) pw = 32;
        const float* Mp = Minv + p * 1024;
        for (int idx = tid; idx < 1024; idx += 320) {
            int i = idx >> 5, j = idx & 31;
            mv[i*33 + j] = Mp[i*32 + j];
        }
        __syncthreads();
        if (tid < 32) {
            float y = 0.f;
            #pragma unroll 8
            for (int j = 0; j < 32; j++) y += mv[lane*33 + j] * sy[col0 + j];
            __syncwarp();
            if (lane < pw) sy[col0 + lane] = y;
        }
        __syncthreads();
        int rem = NEQX - col0 - pw;
        if (tid < rem) {
            int i = col0 + pw + tid;
            float s = 0.f;
            #pragma unroll 8
            for (int c = 0; c < 32; c++)
                if (c < pw) s += S[(col0 + c)*LDSM + i] * sy[col0 + c];
            sy[i] -= s;
        }
        __syncthreads();
    }
    for (int p = NPAN - 1; p >= 0; p--) {
        int col0 = p * 32;
        int pw = NEQX - col0; if (pw > 32) pw = 32;
        const float* Mp = Minv + p * 1024;
        for (int idx = tid; idx < 1024; idx += 320) {
            int i = idx >> 5, j = idx & 31;
            mv[i*33 + j] = Mp[i*32 + j];
        }
        __syncthreads();
        if (tid < 32) {
            float x = 0.f;
            #pragma unroll 8
            for (int j = 0; j < 32; j++) x += mv[j*33 + lane] * sy[col0 + j];
            __syncwarp();
            if (lane < pw) sy[col0 + lane] = x;
        }
        __syncthreads();
        if (tid < col0) {
            float s = 0.f;
            #pragma unroll 8
            for (int c = 0; c < 32; c++)
                if (c < pw) s += S[(col0 + c)*LDSM + tid] * sy[col0 + c];
            sy[tid] -= s;
        }
        __syncthreads();
    }
    if (tid < NEQX) out[tid] = sy[tid];
}

// ---------------- fused trsolve + step (+ mu); ALL Minv panels resident ----
__global__ void __launch_bounds__(768) k_stepsolve(const float* __restrict__ A) {
    int b = blockIdx.x, tid = threadIdx.x, lane = tid & 31;
    const float* S    = g_Smat + b*SSTR;
    const float* Minv = g_Minv + b*(NPAN*1024);
    __shared__ float sy[320];
    __shared__ float miAll[NPAN*32*33];   // 42.2 KB: all 10 panel inverses
    __shared__ float red[32];
    if (tid < 320) sy[tid] = (tid < NEQX) ? g_RHS[b*NEQX + tid] : 0.f;
    for (int idx = tid; idx < NPAN*1024; idx += 768) {
        int p = idx >> 10;
        int e = idx & 1023;
        miAll[p*(32*33) + (e >> 5)*33 + (e & 31)] = Minv[idx];
    }
    __syncthreads();

    // forward: L y = rhs
    for (int p = 0; p < NPAN; p++) {
        int col0 = p * 32;
        int pw = NEQX - col0; if (pw > 32) pw = 32;
        const float* mv = miAll + p*(32*33);
        if (tid < 32) {
            float y = 0.f;
            #pragma unroll 8
            for (int j = 0; j < 32; j++) y += mv[lane*33 + j] * sy[col0 + j];
            __syncwarp();
            if (lane < pw) sy[col0 + lane] = y;
        }
        __syncthreads();
        int rem = NEQX - col0 - pw;
        if (tid < rem) {
            int i = col0 + pw + tid;
            float s = 0.f;
            #pragma unroll 8
            for (int c = 0; c < 32; c++)
                if (c < pw) s += S[(col0 + c)*LDSM + i] * sy[col0 + c];
            sy[i] -= s;
        }
        __syncthreads();
    }
    // backward: L^T x = y
    for (int p = NPAN - 1; p >= 0; p--) {
        int col0 = p * 32;
        int pw = NEQX - col0; if (pw > 32) pw = 32;
        const float* mv = miAll + p*(32*33);
        if (tid < 32) {
            float x = 0.f;
            #pragma unroll 8
            for (int j = 0; j < 32; j++) x += mv[j*33 + lane] * sy[col0 + j];
            __syncwarp();
            if (lane < pw) sy[col0 + lane] = x;
        }
        __syncthreads();
        if (tid < col0) {
            float s = 0.f;
            #pragma unroll 8
            for (int c = 0; c < 32; c++)
                if (c < pw) s += S[(col0 + c)*LDSM + tid] * sy[col0 + c];
            sy[tid] -= s;
        }
        __syncthreads();
    }
    // sy now holds dnu

    // step phase
    float cand = BIGV;
    float t = 0.f, dz = 0.f, ds = 0.f, dlam = 0.f, si = 0.f, li = 0.f;
    if (tid < NXX) {
        #pragma unroll 8
        for (int j = 0; j < NEQX; j++) t += A[j*NXX + tid] * sy[j];
        float r1   = g_R1 [b*NXX + tid];
        float hinv = g_HINV[b*NXX + tid];
        float rp   = g_RP [b*NXX + tid];
        float rs   = g_RS [b*NXX + tid];
        si = g_Sl[b*NXX + tid];
        li = g_Lm[b*NXX + tid];
        dz = (r1 - t) * hinv;
        ds = dz - rp;
        dlam = (-rs - li*ds) / si;
        if (ds   < 0.f) cand = fminf(cand, -si/ds);
        if (dlam < 0.f) cand = fminf(cand, -li/dlam);
    }
    float am = blkMin(cand, red);
    float alpha = fminf(1.0f, 0.99f * am);
    float part = 0.f;
    if (tid < NXX) {
        float sn = si + alpha * ds;
        float ln = li + alpha * dlam;
        g_Z [b*NXX + tid] += alpha * dz;
        g_Sl[b*NXX + tid]  = sn;
        g_Lm[b*NXX + tid]  = ln;
        g_Qt[b*NXX + tid] += alpha * t;
        part = sn * ln;
    }
    if (tid < NEQX) g_NU[b*NEQX + tid] += alpha * sy[tid];
    float dot = blkSum(part, red);
    if (tid == 0) g_MU[b] = dot * (1.0f / (float)NXX);
}

// ---------------- init rhs ----------------
__global__ void __launch_bounds__(768) k_rhs0(const float* __restrict__ A, const float* __restrict__ bv) {
    int b = blockIdx.x, tid = threadIdx.x;
    __shared__ float su[NXX];
    if (tid < NXX) su[tid] = g_P[b*NXX + tid] * g_Hinv0[tid];
    __syncthreads();
    int w = tid >> 5, lane = tid & 31;
    for (int g = w; g < NEQX/4; g += 24) {
        int j = g * 4;
        const float* A0 = A + (size_t)j*NXX;
        float s0=0.f, s1=0.f, s2=0.f, s3=0.f;
        for (int k = lane; k < NXX; k += 32) {
            float u = su[k];
            s0 += A0[k]         * u;
            s1 += A0[NXX + k]   * u;
            s2 += A0[2*NXX + k] * u;
            s3 += A0[3*NXX + k] * u;
        }
        #pragma unroll
        for (int o = 16; o; o >>= 1) {
            s0 += __shfl_xor_sync(0xffffffffu, s0, o);
            s1 += __shfl_xor_sync(0xffffffffu, s1, o);
            s2 += __shfl_xor_sync(0xffffffffu, s2, o);
            s3 += __shfl_xor_sync(0xffffffffu, s3, o);
        }
        if (lane == 0) {
            g_RHS[b*NEQX + j]     = -s0 - bv[j];
            g_RHS[b*NEQX + j + 1] = -s1 - bv[j+1];
            g_RHS[b*NEQX + j + 2] = -s2 - bv[j+2];
            g_RHS[b*NEQX + j + 3] = -s3 - bv[j+3];
        }
    }
}

// ---------------- init z, s, lam, q (+ mu) ----------------
__global__ void __launch_bounds__(768) k_initz(const float* __restrict__ A, const float* __restrict__ h) {
    int b = blockIdx.x, tid = threadIdx.x;
    __shared__ float snu[NEQX];
    __shared__ float red[32];
    if (tid < NEQX) snu[tid] = g_NU[b*NEQX + tid];
    __syncthreads();
    float part = 0.f;
    if (tid < NXX) {
        float q = 0.f;
        #pragma unroll 8
        for (int j = 0; j < NEQX; j++) q += A[j*NXX + tid] * snu[j];
        float z = (-g_P[b*NXX + tid] - q) * g_Hinv0[tid];
        float s = fmaxf(h[tid] + z, 1.0f);
        g_Qt[b*NXX + tid] = q;
        g_Z [b*NXX + tid] = z;
        g_Sl[b*NXX + tid] = s;
        g_Lm[b*NXX + tid] = 1.0f;
        part = s;
    }
    float dot = blkSum(part, red);
    if (tid == 0) g_MU[b] = dot * (1.0f / (float)NXX);
}

// ---------------- per-iteration residuals + dnu RHS (wide: 4 CTAs/batch) ---
__global__ void __launch_bounds__(768) k_res(const float* __restrict__ A,
                                             const float* __restrict__ bv,
                                             const float* __restrict__ h) {
    int x = blockIdx.x, b = blockIdx.y, tid = threadIdx.x;
    __shared__ float su[NXX];
    float mu = g_MU[b];
    if (tid < NXX) {
        float si = g_Sl[b*NXX + tid];
        float li = g_Lm[b*NXX + tid];
        float zi = g_Z[b*NXX + tid];
        float pi = g_P[b*NXX + tid];
        float qi = g_Qt[b*NXX + tid];
        float qd = g_Qd[tid];
        float hi = h[tid];
        float rz = qd*zi + pi - li + qi;
        float rp = si - zi - hi;
        float rs = si*li - SIGC*mu;
        float hd = qd + li/si;
        float hinv = 1.0f/hd;
        float r1 = -rz + (li*rp - rs)/si;
        if (x == 0) {
            g_HINV[b*NXX + tid] = hinv;
            g_R1 [b*NXX + tid] = r1;
            g_RP [b*NXX + tid] = rp;
            g_RS [b*NXX + tid] = rs;
        }
        su[tid] = r1*hinv + zi;
    }
    __syncthreads();
    int w = tid >> 5, lane = tid & 31;
    int g = x * 24 + w;                 // 4 CTAs x 24 warps = 96 slots >= 75 groups
    if (g < NEQX/4) {
        int j = g * 4;
        const float* A0 = A + (size_t)j*NXX;
        float s0=0.f, s1=0.f, s2=0.f, s3=0.f;
        for (int k = lane; k < NXX; k += 32) {
            float u = su[k];
            s0 += A0[k]         * u;
            s1 += A0[NXX + k]   * u;
            s2 += A0[2*NXX + k] * u;
            s3 += A0[3*NXX + k] * u;
        }
        #pragma unroll
        for (int o = 16; o; o >>= 1) {
            s0 += __shfl_xor_sync(0xffffffffu, s0, o);
            s1 += __shfl_xor_sync(0xffffffffu, s1, o);
            s2 += __shfl_xor_sync(0xffffffffu, s2, o);
            s3 += __shfl_xor_sync(0xffffffffu, s3, o);
        }
        if (lane == 0) {
            g_RHS[b*NEQX + j]     = s0 - bv[j];
            g_RHS[b*NEQX + j + 1] = s1 - bv[j+1];
            g_RHS[b*NEQX + j + 2] = s2 - bv[j+2];
            g_RHS[b*NEQX + j + 3] = s3 - bv[j+3];
        }
    }
}

// ---------------- output copy ----------------
__global__ void k_out(float* __restrict__ out) {
    int b = blockIdx.x, i = threadIdx.x;
    if (i < NXX) out[b*NXX + i] = g_Z[b*NXX + i];
}

// ---------------- launch ----------------
extern "C" void kernel_launch(void* const* d_in, const int* in_sizes, int n_in,
                              void* d_out, int out_size) {
    const float* puzzles = (const float*)d_in[0];
    const float* Q       = (const float*)d_in[1];
    const float* h       = (const float*)d_in[3];
    const float* A       = (const float*)d_in[4];
    const float* bvec    = (const float*)d_in[5];
    float* out = (float*)d_out;

    // init
    k_setup  <<<BAT, 768>>>(puzzles, Q);
    k_syrk   <<<dim3(15, 1), 256>>>(A, 1);
    k_chol   <<<CLW, 256>>>(1);
    k_rhs0   <<<BAT, 768>>>(A, bvec);
    k_trsolve<<<BAT, 320>>>(1);
    k_initz  <<<BAT, 768>>>(A, h);

    // 10 PDIPM iterations
    for (int it = 0; it < 10; it++) {
        k_res      <<<dim3(4, BAT), 768>>>(A, bvec, h);
        k_syrk     <<<dim3(15, BAT), 256>>>(A, 0);
        k_chol     <<<BAT*CLW, 256>>>(0);
        k_stepsolve<<<BAT, 768>>>(A);
    }
    k_out<<<BAT, 768>>>(out);
}